// round 12
// baseline (speedup 1.0000x reference)
#include <cuda_runtime.h>
#include <cuda_bf16.h>

// RippleNet: H=2, B=2048, M=64, D=16, N_ENT=500000, N_REL=32
// inputs: items[B] i32, heads[H,B,M] i32, relations[H,B,M] i32,
//         tails[H,B,M] i32, ent_emb[N_ENT,16] f32, rel_emb[32,16,16] f32
// output: predicts[B] f32

#define B_ 2048
#define M_ 64
#define D_ 16
#define NREL_ 32
#define RS 20   // staged row stride in floats: 80B, 16B-aligned for cp.async
#define QS 20   // q row stride

// One block per b, 128 threads.
// Phase 1: quad-coalesced cp.async.cg gathers (head+tail rows) -> smem,
//          NO destination registers (kills long-scoreboard stalls).
// Phase 2: octet q-phase (R9) overlaps the in-flight cp.async group.
// Phase 3: thread t owns row t: full-row dots from smem, zero dot shuffles.
__global__ __launch_bounds__(128, 8) void ripple_kernel(
    const int* __restrict__ items,
    const int* __restrict__ heads,
    const int* __restrict__ rels,
    const int* __restrict__ tails,
    const float* __restrict__ ent,
    const float* __restrict__ rel,
    float* __restrict__ out)
{
    const int b    = blockIdx.x;
    const int tid  = threadIdx.x;
    const int quad = tid >> 2;
    const int ch   = tid & 3;
    const int j0   = ch * 4;

    __shared__ __align__(16) float rows_s[256 * RS];  // [0..127] head, [128..255] tail
    __shared__ __align__(16) float q[NREL_ * QS];
    __shared__ __align__(16) float item_s[D_];
    __shared__ int    idxh_s[128], idxr_s[128], idxt_s[128];
    __shared__ float2 wsum[4];

    // ---- coalesced index staging (3 LDG.32/thread) ----
    {
        const int base = (tid >> 6) * (B_ * M_) + b * M_ + (tid & 63);
        idxh_s[tid] = __ldg(heads + base);
        idxr_s[tid] = __ldg(rels  + base);
        idxt_s[tid] = __ldg(tails + base);
    }
    const int it = items[b];
    if (tid < D_) item_s[tid] = __ldg(ent + (size_t)it * D_ + tid);
    __syncthreads();

    // ---- phase 1: async gathers, 8 x cp.async.cg 16B per thread ----
    #pragma unroll
    for (int k = 0; k < 4; k++) {
        const int row = quad + 32 * k;
        const unsigned dst = (unsigned)__cvta_generic_to_shared(&rows_s[row * RS + j0]);
        const float* src = ent + (size_t)idxh_s[row] * D_ + j0;
        asm volatile("cp.async.cg.shared.global [%0], [%1], 16;" :: "r"(dst), "l"(src));
    }
    #pragma unroll
    for (int k = 0; k < 4; k++) {
        const int row = quad + 32 * k;
        const unsigned dst = (unsigned)__cvta_generic_to_shared(&rows_s[(128 + row) * RS + j0]);
        const float* src = ent + (size_t)idxt_s[row] * D_ + j0;
        asm volatile("cp.async.cg.shared.global [%0], [%1], 16;" :: "r"(dst), "l"(src));
    }
    asm volatile("cp.async.commit_group;");

    // ---- phase 2: octet q-phase (one 128B rel line per instr), overlaps gathers ----
    {
        const int lane = tid & 31;
        const int O    = (tid >> 5) * 4 + ((lane >> 3) & 3);   // octet 0..15
        const int half = (lane >> 2) & 1;
        #pragma unroll
        for (int rr = 0; rr < 2; rr++) {
            const int r = O + 16 * rr;
            const float4* Rp = (const float4*)(rel + r * (D_ * D_)) + ch;
            float4 acc = make_float4(0.f, 0.f, 0.f, 0.f);
            #pragma unroll
            for (int k = 0; k < 8; k++) {
                const int i = 2 * k + half;
                const float4 rv = Rp[i * 4];
                const float  wi = item_s[i];
                acc.x = fmaf(wi, rv.x, acc.x);
                acc.y = fmaf(wi, rv.y, acc.y);
                acc.z = fmaf(wi, rv.z, acc.z);
                acc.w = fmaf(wi, rv.w, acc.w);
            }
            acc.x += __shfl_xor_sync(0xffffffffu, acc.x, 4);
            acc.y += __shfl_xor_sync(0xffffffffu, acc.y, 4);
            acc.z += __shfl_xor_sync(0xffffffffu, acc.z, 4);
            acc.w += __shfl_xor_sync(0xffffffffu, acc.w, 4);
            if (half == 0)
                *(float4*)&q[r * QS + j0] = acc;
        }
    }

    asm volatile("cp.async.wait_group 0;" ::: "memory");
    __syncthreads();   // rows_s + q visible to all

    // ---- phase 3: thread t owns row t — full-row dots, no shuffles ----
    const float4 i0 = *(const float4*)&item_s[0];
    const float4 i1 = *(const float4*)&item_s[4];
    const float4 i2 = *(const float4*)&item_s[8];
    const float4 i3 = *(const float4*)&item_s[12];

    const int   r  = idxr_s[tid];
    const float4 q0 = *(const float4*)&q[r * QS + 0];
    const float4 q1 = *(const float4*)&q[r * QS + 4];
    const float4 q2 = *(const float4*)&q[r * QS + 8];
    const float4 q3 = *(const float4*)&q[r * QS + 12];

    const float* hr = &rows_s[tid * RS];
    const float4 h0 = *(const float4*)(hr + 0);
    const float4 h1 = *(const float4*)(hr + 4);
    const float4 h2 = *(const float4*)(hr + 8);
    const float4 h3 = *(const float4*)(hr + 12);

    float l = 0.f;
    l = fmaf(q0.x, h0.x, l); l = fmaf(q0.y, h0.y, l);
    l = fmaf(q0.z, h0.z, l); l = fmaf(q0.w, h0.w, l);
    l = fmaf(q1.x, h1.x, l); l = fmaf(q1.y, h1.y, l);
    l = fmaf(q1.z, h1.z, l); l = fmaf(q1.w, h1.w, l);
    l = fmaf(q2.x, h2.x, l); l = fmaf(q2.y, h2.y, l);
    l = fmaf(q2.z, h2.z, l); l = fmaf(q2.w, h2.w, l);
    l = fmaf(q3.x, h3.x, l); l = fmaf(q3.y, h3.y, l);
    l = fmaf(q3.z, h3.z, l); l = fmaf(q3.w, h3.w, l);

    const float* tr = &rows_s[(128 + tid) * RS];
    const float4 t0 = *(const float4*)(tr + 0);
    const float4 t1 = *(const float4*)(tr + 4);
    const float4 t2 = *(const float4*)(tr + 8);
    const float4 t3 = *(const float4*)(tr + 12);

    float s = 0.f;
    s = fmaf(i0.x, t0.x, s); s = fmaf(i0.y, t0.y, s);
    s = fmaf(i0.z, t0.z, s); s = fmaf(i0.w, t0.w, s);
    s = fmaf(i1.x, t1.x, s); s = fmaf(i1.y, t1.y, s);
    s = fmaf(i1.z, t1.z, s); s = fmaf(i1.w, t1.w, s);
    s = fmaf(i2.x, t2.x, s); s = fmaf(i2.y, t2.y, s);
    s = fmaf(i2.z, t2.z, s); s = fmaf(i2.w, t2.w, s);
    s = fmaf(i3.x, t3.x, s); s = fmaf(i3.y, t3.y, s);
    s = fmaf(i3.z, t3.z, s); s = fmaf(i3.w, t3.w, s);

    // ---- softmax w/o max subtraction (|l| ~ 0.1; exp safe, identical math).
    //      Warp w holds rows 32w..32w+31 (same hop): plain warp reduce. ----
    const float e = __expf(l);
    float se  = e;
    float ses = e * s;
    #pragma unroll
    for (int off = 16; off; off >>= 1) {
        se  += __shfl_xor_sync(0xffffffffu, se,  off);
        ses += __shfl_xor_sync(0xffffffffu, ses, off);
    }
    if ((tid & 31) == 0)
        wsum[tid >> 5] = make_float2(se, ses);
    __syncthreads();

    if (tid == 0) {
        const float x = (wsum[0].y + wsum[1].y) / (wsum[0].x + wsum[1].x)
                      + (wsum[2].y + wsum[3].y) / (wsum[2].x + wsum[3].x);
        out[b] = 1.f / (1.f + __expf(-x));
    }
}

extern "C" void kernel_launch(void* const* d_in, const int* in_sizes, int n_in,
                              void* d_out, int out_size) {
    const int*   items = (const int*)  d_in[0];
    const int*   heads = (const int*)  d_in[1];
    const int*   rels  = (const int*)  d_in[2];
    const int*   tails = (const int*)  d_in[3];
    const float* ent   = (const float*)d_in[4];
    const float* rel   = (const float*)d_in[5];
    float* out = (float*)d_out;

    ripple_kernel<<<B_, 128>>>(items, heads, rels, tails, ent, rel, out);
}